// round 2
// baseline (speedup 1.0000x reference)
#include <cuda_runtime.h>

#define BB 16
#define PP 16
#define II 16
#define LL 64
#define DD 128
#define FF 128
#define CC 1024
#define NEGV -1000000000.0f

// Scratch (no allocations allowed)
__device__ float g_inst[BB*PP*II*FF];   // (b,p,i,f)
__device__ float g_meta[BB*PP*FF];      // (b,p,f)
__device__ float g_base[BB];            // per-batch score base

// ---------------------------------------------------------------------------
// K1: masked mean over L + conv (1x1) -> g_inst.  One block per (b,p).
// ---------------------------------------------------------------------------
__global__ void __launch_bounds__(256) k1_mean_conv(
    const float* __restrict__ path_emb,
    const int*   __restrict__ path_len,
    const float* __restrict__ conv_w,
    const float* __restrict__ conv_b)
{
    __shared__ float mean_sh[16*132];   // [i][d], stride 132 (float4-aligned)
    int bp = blockIdx.x;
    int t = threadIdx.x, wid = t >> 5, lane = t & 31;

    // masked means: warp w handles instances i = w, w+8 (float4 coalesced)
    for (int i = wid; i < II; i += 8) {
        int len = path_len[bp*II + i];
        const float4* pe = (const float4*)path_emb + (size_t)(bp*II + i) * (LL*DD/4);
        float4 acc = make_float4(0.f,0.f,0.f,0.f);
        #pragma unroll 4
        for (int l = 0; l < len; l++) {
            float4 e = pe[l*32 + lane];
            acc.x += e.x; acc.y += e.y; acc.z += e.z; acc.w += e.w;
        }
        float inv = 1.0f / (float)len;
        ((float4*)(mean_sh + i*132))[lane] =
            make_float4(acc.x*inv, acc.y*inv, acc.z*inv, acc.w*inv);
    }
    __syncthreads();

    // inst[i][f] = mean[i] . conv_w[f] + conv_b[f]  (warp-dot, coalesced rows)
    for (int f = wid; f < FF; f += 8) {
        float4 w4 = ((const float4*)(conv_w + f*DD))[lane];
        float cb = conv_b[f];
        #pragma unroll
        for (int i = 0; i < II; i++) {
            const float* mrow = mean_sh + i*132;
            float s = w4.x*mrow[lane*4+0] + w4.y*mrow[lane*4+1]
                    + w4.z*mrow[lane*4+2] + w4.w*mrow[lane*4+3];
            #pragma unroll
            for (int o = 16; o > 0; o >>= 1) s += __shfl_xor_sync(0xffffffffu, s, o);
            if (lane == 0) g_inst[(bp*II + i)*FF + f] = s + cb;
        }
    }
}

// ---------------------------------------------------------------------------
// Shared MHA core: 16x128 input in xs (stride 129), 384 threads.
// Produces y_sh[128] = mean_over_rows(softmax(qk^T/sqrt(128)) @ v).
// rA (6528 floats) is a union: weight staging buf [384][17] then qkv [16][385].
// ---------------------------------------------------------------------------
__device__ __forceinline__ void mha_core(
    const float* __restrict__ in_w, const float* __restrict__ in_b,
    float* xs, float* rA, float* attn_sh, float* a_sh, float* y_sh)
{
    int t = threadIdx.x;  // 0..383, also the qkv output column
    float acc[16];
    #pragma unroll
    for (int i = 0; i < 16; i++) acc[i] = 0.f;

    // qkv = x @ in_w.T : stage 16-wide K-chunks of in_w into shared (coalesced),
    // then broadcast-FMA from shared (conflict-free: pad 17, pad 129).
    for (int kk0 = 0; kk0 < 128; kk0 += 16) {
        for (int idx = t; idx < 384*16; idx += 384) {
            int col = idx >> 4, ko = idx & 15;
            rA[col*17 + ko] = in_w[col*128 + kk0 + ko];
        }
        __syncthreads();
        #pragma unroll
        for (int ko = 0; ko < 16; ko++) {
            float wv = rA[t*17 + ko];
            #pragma unroll
            for (int i = 0; i < 16; i++)
                acc[i] = fmaf(xs[i*129 + kk0 + ko], wv, acc[i]);
        }
        __syncthreads();
    }
    // write qkv into rA (stride 385 -> conflict-free column reads)
    float bias = in_b[t];
    #pragma unroll
    for (int i = 0; i < 16; i++) rA[i*385 + t] = acc[i] + bias;
    __syncthreads();

    // attention scores (16x16)
    if (t < 256) {
        int i = t >> 4, j = t & 15;
        float s = 0.f;
        #pragma unroll
        for (int kk = 0; kk < 128; kk++)
            s = fmaf(rA[i*385 + kk], rA[j*385 + 128 + kk], s);
        attn_sh[i*17 + j] = s * 0.08838834764831845f;  // 1/sqrt(128)
    }
    __syncthreads();

    // row softmax (16 rows, 1 thread each)
    if (t < 16) {
        float mx = -3.4e38f;
        #pragma unroll
        for (int j = 0; j < 16; j++) mx = fmaxf(mx, attn_sh[t*17 + j]);
        float sum = 0.f;
        #pragma unroll
        for (int j = 0; j < 16; j++) {
            float e = __expf(attn_sh[t*17 + j] - mx);
            attn_sh[t*17 + j] = e; sum += e;
        }
        float inv = 1.f / sum;
        #pragma unroll
        for (int j = 0; j < 16; j++) attn_sh[t*17 + j] *= inv;
    }
    __syncthreads();

    // a[j] = mean_i attn[i][j]
    if (t < 16) {
        float s = 0.f;
        #pragma unroll
        for (int i = 0; i < 16; i++) s += attn_sh[i*17 + t];
        a_sh[t] = s * (1.f/16.f);
    }
    __syncthreads();

    // y[f] = sum_j a[j] * v[j][f]
    if (t < 128) {
        float s = 0.f;
        #pragma unroll
        for (int j = 0; j < 16; j++)
            s = fmaf(a_sh[j], rA[j*385 + 256 + t], s);
        y_sh[t] = s;
    }
    __syncthreads();
}

__device__ __forceinline__ float warp_dot128(const float* __restrict__ wrow,
                                             const float* vsh, int lane)
{
    float4 w4 = ((const float4*)wrow)[lane];
    float s = w4.x*vsh[lane*4+0] + w4.y*vsh[lane*4+1]
            + w4.z*vsh[lane*4+2] + w4.w*vsh[lane*4+3];
    #pragma unroll
    for (int o = 16; o > 0; o >>= 1) s += __shfl_xor_sync(0xffffffffu, s, o);
    return s;
}

// ---------------------------------------------------------------------------
// K2: pia MHA per (b,p) -> g_meta.  256 blocks x 384 threads.
// ---------------------------------------------------------------------------
__global__ void __launch_bounds__(384) k2_pia(
    const float* __restrict__ in_w, const float* __restrict__ in_b,
    const float* __restrict__ out_w, const float* __restrict__ out_b)
{
    __shared__ float xs[16*129];
    __shared__ float rA[6528];
    __shared__ float attn_sh[16*17];
    __shared__ float a_sh[16];
    __shared__ float y_sh[128];
    int bp = blockIdx.x, t = threadIdx.x;

    for (int idx = t; idx < 2048; idx += 384) {
        int i = idx >> 7, d = idx & 127;
        xs[i*129 + d] = g_inst[bp*2048 + idx];
    }
    __syncthreads();
    mha_core(in_w, in_b, xs, rA, attn_sh, a_sh, y_sh);

    int wid = t >> 5, lane = t & 31;
    for (int f = wid; f < 128; f += 12) {
        float s = warp_dot128(out_w + f*128, y_sh, lane);
        if (lane == 0) g_meta[bp*128 + f] = s + out_b[f];
    }
}

// ---------------------------------------------------------------------------
// K3: mpa MHA per b + qia affine branch + score base.  16 blocks x 384 thr.
// ---------------------------------------------------------------------------
__global__ void __launch_bounds__(384) k3_mpa(
    const float* __restrict__ mpa_in_w, const float* __restrict__ mpa_in_b,
    const float* __restrict__ mpa_out_w, const float* __restrict__ mpa_out_b,
    const float* __restrict__ qia_in_w, const float* __restrict__ qia_in_b,
    const float* __restrict__ qia_out_w, const float* __restrict__ qia_out_b,
    const float* __restrict__ query,
    const float* __restrict__ score_w, const float* __restrict__ score_b)
{
    __shared__ float xs[16*129];
    __shared__ float rA[6528];
    __shared__ float attn_sh[16*17];
    __shared__ float a_sh[16];
    __shared__ float y_sh[128];
    __shared__ float v1_sh[128], mm_sh[128], t_sh[128], v2_sh[128], red[128];
    int b = blockIdx.x, t = threadIdx.x;

    for (int idx = t; idx < 2048; idx += 384) {
        int i = idx >> 7, d = idx & 127;
        xs[i*129 + d] = g_meta[b*2048 + idx];
    }
    __syncthreads();
    mha_core(mpa_in_w, mpa_in_b, xs, rA, attn_sh, a_sh, y_sh);

    int wid = t >> 5, lane = t & 31;
    // v1 = y @ mpa_out_w.T + b
    for (int f = wid; f < 128; f += 12) {
        float s = warp_dot128(mpa_out_w + f*128, y_sh, lane);
        if (lane == 0) v1_sh[f] = s + mpa_out_b[f];
    }
    // meta mean over P
    if (t < 128) {
        float s = 0.f;
        #pragma unroll
        for (int i = 0; i < 16; i++) s += xs[i*129 + t];
        mm_sh[t] = s * (1.f/16.f);
    }
    __syncthreads();
    // t = mm @ Wv.T + bv   (qia V-projection rows [2F:3F])
    for (int f = wid; f < 128; f += 12) {
        float s = warp_dot128(qia_in_w + (256 + f)*128, mm_sh, lane);
        if (lane == 0) t_sh[f] = s + qia_in_b[256 + f];
    }
    __syncthreads();
    // v2 = t @ qia_out_w.T + b
    for (int f = wid; f < 128; f += 12) {
        float s = warp_dot128(qia_out_w + f*128, t_sh, lane);
        if (lane == 0) v2_sh[f] = s + qia_out_b[f];
    }
    __syncthreads();
    // base[b] = q.swq + v1.sw1 + v2.sw2 + score_b
    if (t < 128)
        red[t] = query[b*128 + t]*score_w[t]
               + v1_sh[t]*score_w[128 + t]
               + v2_sh[t]*score_w[256 + t];
    __syncthreads();
    for (int off = 64; off > 0; off >>= 1) {
        if (t < off) red[t] += red[t + off];
        __syncthreads();
    }
    if (t == 0) g_base[b] = red[0] + score_b[0];
}

// ---------------------------------------------------------------------------
// K4: candidate scores -> logits in d_out. Warp per candidate dot; masked
// candidates skip the cand_emb load entirely (~half the HBM traffic).
// ---------------------------------------------------------------------------
__global__ void __launch_bounds__(256) k4_scores(
    const float* __restrict__ cand_emb,
    const int*   __restrict__ cand_len,
    const float* __restrict__ score_w,
    float* __restrict__ out)
{
    int bp = blockIdx.x >> 3, chunk = blockIdx.x & 7;
    int t = threadIdx.x, wid = t >> 5, lane = t & 31;
    float4 w4 = ((const float4*)(score_w + 384))[lane];
    int b = bp >> 4, p = bp & 15;
    float baseb = g_base[b];
    int clen = cand_len[bp];
    const float4* ce = (const float4*)cand_emb + (size_t)bp * (CC*DD/4);
    float* orow = out + b*(PP*CC) + p*CC;
    int c0 = chunk*128 + wid*16;
    #pragma unroll
    for (int cc = 0; cc < 16; cc++) {
        int c = c0 + cc;
        if (c < clen) {
            float4 e = ce[c*32 + lane];
            float s = e.x*w4.x + e.y*w4.y + e.z*w4.z + e.w*w4.w;
            #pragma unroll
            for (int o = 16; o > 0; o >>= 1) s += __shfl_xor_sync(0xffffffffu, s, o);
            if (lane == 0) orow[c] = baseb + s;
        } else if (lane == 0) {
            orow[c] = NEGV;
        }
    }
}

// ---------------------------------------------------------------------------
// K5: softmax over 16384 logits per batch, in-place on d_out. 16 blocks.
// ---------------------------------------------------------------------------
__global__ void __launch_bounds__(512) k5_softmax(float* __restrict__ out)
{
    __shared__ float sred[16];
    int b = blockIdx.x, t = threadIdx.x;
    int lane = t & 31, wid = t >> 5;
    float* row = out + b*16384;
    float v[32];
    float mx = -3.4e38f;
    #pragma unroll
    for (int r = 0; r < 32; r++) { v[r] = row[t + 512*r]; mx = fmaxf(mx, v[r]); }
    #pragma unroll
    for (int o = 16; o > 0; o >>= 1) mx = fmaxf(mx, __shfl_xor_sync(0xffffffffu, mx, o));
    if (lane == 0) sred[wid] = mx;
    __syncthreads();
    if (wid == 0) {
        float m = (lane < 16) ? sred[lane] : -3.4e38f;
        #pragma unroll
        for (int o = 16; o > 0; o >>= 1) m = fmaxf(m, __shfl_xor_sync(0xffffffffu, m, o));
        if (lane == 0) sred[0] = m;
    }
    __syncthreads();
    mx = sred[0];
    __syncthreads();
    float sum = 0.f;
    #pragma unroll
    for (int r = 0; r < 32; r++) { v[r] = __expf(v[r] - mx); sum += v[r]; }
    #pragma unroll
    for (int o = 16; o > 0; o >>= 1) sum += __shfl_xor_sync(0xffffffffu, sum, o);
    if (lane == 0) sred[wid] = sum;
    __syncthreads();
    if (wid == 0) {
        float s = (lane < 16) ? sred[lane] : 0.f;
        #pragma unroll
        for (int o = 16; o > 0; o >>= 1) s += __shfl_xor_sync(0xffffffffu, s, o);
        if (lane == 0) sred[0] = s;
    }
    __syncthreads();
    float inv = 1.f / sred[0];
    #pragma unroll
    for (int r = 0; r < 32; r++) row[t + 512*r] = v[r] * inv;
}

// ---------------------------------------------------------------------------
extern "C" void kernel_launch(void* const* d_in, const int* in_sizes, int n_in,
                              void* d_out, int out_size)
{
    const float* query     = (const float*)d_in[0];
    const float* path_emb  = (const float*)d_in[1];
    const int*   path_len  = (const int*)  d_in[2];
    const float* cand_emb  = (const float*)d_in[3];
    const int*   cand_len  = (const int*)  d_in[4];
    const float* conv_w    = (const float*)d_in[5];
    const float* conv_b    = (const float*)d_in[6];
    const float* pia_in_w  = (const float*)d_in[7];
    const float* pia_in_b  = (const float*)d_in[8];
    const float* pia_out_w = (const float*)d_in[9];
    const float* pia_out_b = (const float*)d_in[10];
    const float* mpa_in_w  = (const float*)d_in[11];
    const float* mpa_in_b  = (const float*)d_in[12];
    const float* mpa_out_w = (const float*)d_in[13];
    const float* mpa_out_b = (const float*)d_in[14];
    const float* qia_in_w  = (const float*)d_in[15];
    const float* qia_in_b  = (const float*)d_in[16];
    const float* qia_out_w = (const float*)d_in[17];
    const float* qia_out_b = (const float*)d_in[18];
    const float* score_w   = (const float*)d_in[19];
    const float* score_b   = (const float*)d_in[20];
    float* out = (float*)d_out;

    k1_mean_conv<<<BB*PP, 256>>>(path_emb, path_len, conv_w, conv_b);
    k2_pia<<<BB*PP, 384>>>(pia_in_w, pia_in_b, pia_out_w, pia_out_b);
    k3_mpa<<<BB, 384>>>(mpa_in_w, mpa_in_b, mpa_out_w, mpa_out_b,
                        qia_in_w, qia_in_b, qia_out_w, qia_out_b,
                        query, score_w, score_b);
    k4_scores<<<BB*PP*8, 256>>>(cand_emb, cand_len, score_w, out);
    k5_softmax<<<BB, 512>>>(out);
}

// round 3
// speedup vs baseline: 8.1467x; 8.1467x over previous
#include <cuda_runtime.h>

#define BB 16
#define PP 16
#define CC 1024
#define DD 128
#define NEGV -1000000000.0f

// ---------------------------------------------------------------------------
// kS: logits[b,p,c] = cand_emb[b,p,c] . score_w[384:512]  (valid), NEG (masked).
// All other network terms are row-constant in the softmax and cancel exactly;
// masked entries underflow to exactly 0 in both reference and kernel.
// 1024 blocks x 256 threads; warp handles 32 candidates, 4 at a time for MLP.
// ---------------------------------------------------------------------------
__global__ void __launch_bounds__(256) k_scores(
    const float* __restrict__ cand_emb,
    const int*   __restrict__ cand_len,
    const float* __restrict__ score_w,
    float* __restrict__ out)
{
    int bp = blockIdx.x >> 2, chunk = blockIdx.x & 3;
    int t = threadIdx.x, wid = t >> 5, lane = t & 31;

    float4 w4 = ((const float4*)(score_w + 3*DD))[lane];
    int clen = cand_len[bp];
    const float4* __restrict__ ce =
        (const float4*)cand_emb + (size_t)bp * (CC*DD/4);
    float* __restrict__ orow = out + (size_t)bp * CC;

    int c0 = chunk*256 + wid*32;
    int nv = clen - c0; nv = nv < 0 ? 0 : (nv > 32 ? 32 : nv);

    int j = 0;
    // 4-wide batches: 4 independent LDG.128 in flight before the shuffle chain
    for (; j + 4 <= nv; j += 4) {
        int c = c0 + j;
        float4 e0 = ce[(size_t)(c+0)*32 + lane];
        float4 e1 = ce[(size_t)(c+1)*32 + lane];
        float4 e2 = ce[(size_t)(c+2)*32 + lane];
        float4 e3 = ce[(size_t)(c+3)*32 + lane];
        float s0 = e0.x*w4.x + e0.y*w4.y + e0.z*w4.z + e0.w*w4.w;
        float s1 = e1.x*w4.x + e1.y*w4.y + e1.z*w4.z + e1.w*w4.w;
        float s2 = e2.x*w4.x + e2.y*w4.y + e2.z*w4.z + e2.w*w4.w;
        float s3 = e3.x*w4.x + e3.y*w4.y + e3.z*w4.z + e3.w*w4.w;
        #pragma unroll
        for (int o = 16; o > 0; o >>= 1) {
            s0 += __shfl_xor_sync(0xffffffffu, s0, o);
            s1 += __shfl_xor_sync(0xffffffffu, s1, o);
            s2 += __shfl_xor_sync(0xffffffffu, s2, o);
            s3 += __shfl_xor_sync(0xffffffffu, s3, o);
        }
        if (lane == 0)
            *(float4*)(orow + c) = make_float4(s0, s1, s2, s3);
    }
    // scalar tail
    for (; j < nv; j++) {
        int c = c0 + j;
        float4 e = ce[(size_t)c*32 + lane];
        float s = e.x*w4.x + e.y*w4.y + e.z*w4.z + e.w*w4.w;
        #pragma unroll
        for (int o = 16; o > 0; o >>= 1) s += __shfl_xor_sync(0xffffffffu, s, o);
        if (lane == 0) orow[c] = s;
    }
    // masked tail: one coalesced vector write by all lanes
    int cm = c0 + nv + lane;
    if (cm < c0 + 32) orow[cm] = NEGV;
}

// ---------------------------------------------------------------------------
// k5: softmax over 16384 logits per batch, in-place on d_out. 16 blocks x 512.
// float4 loads/stores; exp(NEG - max) underflows to exactly 0 (matches ref).
// ---------------------------------------------------------------------------
__global__ void __launch_bounds__(512) k5_softmax(float* __restrict__ out)
{
    __shared__ float sred[16];
    int b = blockIdx.x, t = threadIdx.x;
    int lane = t & 31, wid = t >> 5;
    float4* row4 = (float4*)(out + (size_t)b * 16384);

    float4 v[8];
    float mx = -3.4e38f;
    #pragma unroll
    for (int r = 0; r < 8; r++) {
        v[r] = row4[t + 512*r];
        mx = fmaxf(mx, fmaxf(fmaxf(v[r].x, v[r].y), fmaxf(v[r].z, v[r].w)));
    }
    #pragma unroll
    for (int o = 16; o > 0; o >>= 1)
        mx = fmaxf(mx, __shfl_xor_sync(0xffffffffu, mx, o));
    if (lane == 0) sred[wid] = mx;
    __syncthreads();
    if (wid == 0) {
        float m = (lane < 16) ? sred[lane] : -3.4e38f;
        #pragma unroll
        for (int o = 16; o > 0; o >>= 1)
            m = fmaxf(m, __shfl_xor_sync(0xffffffffu, m, o));
        if (lane == 0) sred[0] = m;
    }
    __syncthreads();
    mx = sred[0];
    __syncthreads();

    float sum = 0.f;
    #pragma unroll
    for (int r = 0; r < 8; r++) {
        v[r].x = __expf(v[r].x - mx); sum += v[r].x;
        v[r].y = __expf(v[r].y - mx); sum += v[r].y;
        v[r].z = __expf(v[r].z - mx); sum += v[r].z;
        v[r].w = __expf(v[r].w - mx); sum += v[r].w;
    }
    #pragma unroll
    for (int o = 16; o > 0; o >>= 1)
        sum += __shfl_xor_sync(0xffffffffu, sum, o);
    if (lane == 0) sred[wid] = sum;
    __syncthreads();
    if (wid == 0) {
        float s = (lane < 16) ? sred[lane] : 0.f;
        #pragma unroll
        for (int o = 16; o > 0; o >>= 1)
            s += __shfl_xor_sync(0xffffffffu, s, o);
        if (lane == 0) sred[0] = s;
    }
    __syncthreads();
    float inv = 1.f / sred[0];
    #pragma unroll
    for (int r = 0; r < 8; r++) {
        v[r].x *= inv; v[r].y *= inv; v[r].z *= inv; v[r].w *= inv;
        row4[t + 512*r] = v[r];
    }
}

// ---------------------------------------------------------------------------
extern "C" void kernel_launch(void* const* d_in, const int* in_sizes, int n_in,
                              void* d_out, int out_size)
{
    const float* cand_emb = (const float*)d_in[3];
    const int*   cand_len = (const int*)  d_in[4];
    const float* score_w  = (const float*)d_in[19];
    float* out = (float*)d_out;

    k_scores<<<BB*PP*4, 256>>>(cand_emb, cand_len, score_w, out);
    k5_softmax<<<BB, 512>>>(out);
}